// round 8
// baseline (speedup 1.0000x reference)
#include <cuda_runtime.h>
#include <math.h>

// Problem constants (AirMPRNN: N=50000, E=1e6, T=10, H=8)
#define T_FRAMES 10
#define HID 8
#define MAXN 65536
#define MAXE 1048576

// Scratch (device globals).
__device__ float4 g_h[MAXN * 2];   // hidden: (h0..h3),(h4..h7)
__device__ float  g_v[MAXN];       // per-node edge-message scalar for current frame
__device__ float  g_agg[MAXN];     // scatter accumulator
__device__ float  g_eaT[(size_t)T_FRAMES * MAXE];  // edge_attr transposed [T][E]

struct EdgeW { const float *w1,*b1,*w2,*b2,*w3,*b3; };
struct NodeW { const float *w1,*b1,*w2,*b2,*ow1,*ob1,*ow2,*ob2; };

typedef unsigned long long u64;

__device__ __forceinline__ float sigmoidf_(float s) {
    return __fdividef(1.0f, 1.0f + __expf(-s));
}
__device__ __forceinline__ float tanhf_(float s) {
    return 1.0f - __fdividef(2.0f, __expf(2.0f * s) + 1.0f);
}

// ---- f32x2 packed helpers ----
__device__ __forceinline__ u64 pk2(float a, float b) {
    u64 r; asm("mov.b64 %0, {%1, %2};" : "=l"(r) : "f"(a), "f"(b)); return r;
}
__device__ __forceinline__ void upk2(u64 v, float& a, float& b) {
    asm("mov.b64 {%0, %1}, %2;" : "=f"(a), "=f"(b) : "l"(v));
}
__device__ __forceinline__ u64 ffma2(u64 a, u64 b, u64 c) {
    u64 d; asm("fma.rn.f32x2 %0, %1, %2, %3;" : "=l"(d) : "l"(a), "l"(b), "l"(c)); return d;
}
__device__ __forceinline__ u64 add2(u64 a, u64 b) {
    u64 d; asm("add.rn.f32x2 %0, %1, %2;" : "=l"(d) : "l"(a), "l"(b)); return d;
}
__device__ __forceinline__ u64 relu2(u64 v) {
    float a, b; upk2(v, a, b);
    return pk2(fmaxf(a, 0.f), fmaxf(b, 0.f));
}
__device__ __forceinline__ u64 shflx_u64(u64 v, int m) {
    unsigned lo = (unsigned)v, hi = (unsigned)(v >> 32);
    lo = __shfl_xor_sync(0xFFFFFFFFu, lo, m);
    hi = __shfl_xor_sync(0xFFFFFFFFu, hi, m);
    return ((u64)hi << 32) | lo;
}

// ---------------------------------------------------------------------------
// Full (single-thread) MLP1 eval — used only by init_kernel.
// ---------------------------------------------------------------------------
__device__ __forceinline__ float mlp1_eval(
    const float* in9,
    const u64* sW1p, const u64* sB1p,
    const u64* sW2p, const u64* sB2p,
    const u64* sW3p, float b3)
{
    u64 h[16];
#pragma unroll
    for (int j = 0; j < 16; j++) h[j] = sB1p[j];
#pragma unroll
    for (int k = 0; k < 9; k++) {
        u64 v = pk2(in9[k], in9[k]);
#pragma unroll
        for (int j = 0; j < 16; j++) h[j] = ffma2(v, sW1p[k * 16 + j], h[j]);
    }
#pragma unroll
    for (int j = 0; j < 16; j++) h[j] = relu2(h[j]);

    u64 acc[16];
#pragma unroll
    for (int j = 0; j < 16; j++) acc[j] = sB2p[j];
#pragma unroll
    for (int kp = 0; kp < 16; kp++) {
        float ha, hb; upk2(h[kp], ha, hb);
        u64 va = pk2(ha, ha), vb = pk2(hb, hb);
#pragma unroll
        for (int j = 0; j < 16; j++)
            acc[j] = ffma2(va, sW2p[(2 * kp) * 16 + j], acc[j]);
#pragma unroll
        for (int j = 0; j < 16; j++)
            acc[j] = ffma2(vb, sW2p[(2 * kp + 1) * 16 + j], acc[j]);
    }

    u64 s = pk2(0.f, 0.f);
#pragma unroll
    for (int j = 0; j < 16; j++) s = ffma2(relu2(acc[j]), sW3p[j], s);
    float s0, s1; upk2(s, s0, s1);
    return sigmoidf_(s0 + s1 + b3);
}

// ---------------------------------------------------------------------------
// ea transpose: [E,T] -> [T][E].
// ---------------------------------------------------------------------------
__global__ void __launch_bounds__(256) transpose_ea_kernel(
    const float* __restrict__ ea, int E)
{
    __shared__ float tile[256 * T_FRAMES];
    int base = blockIdx.x * 256;
    int cnt = min(256, E - base);
    int nflt = cnt * T_FRAMES;

    for (int i = threadIdx.x; i < nflt; i += 256)
        tile[i] = ea[(size_t)base * T_FRAMES + i];
    __syncthreads();

#pragma unroll
    for (int t = 0; t < T_FRAMES; t++) {
        if (threadIdx.x < cnt)
            g_eaT[(size_t)t * E + base + threadIdx.x] =
                tile[threadIdx.x * T_FRAMES + t];
    }
}

// ---------------------------------------------------------------------------
// Init: hidden = 0, agg = 0, v0 = sigmoid(MLP1([x0(t=0), 0..0]))
// ---------------------------------------------------------------------------
__global__ void __launch_bounds__(256) init_kernel(
    const float* __restrict__ x, EdgeW W, int N)
{
    __shared__ u64 sW1[9 * 16], sB1[16], sW2[32 * 16], sB2[16], sW3[16];
    float* fW1 = (float*)sW1; float* fB1 = (float*)sB1;
    float* fW2 = (float*)sW2; float* fB2 = (float*)sB2;
    float* fW3 = (float*)sW3;
    for (int i = threadIdx.x; i < 9 * 32; i += blockDim.x)  fW1[i] = W.w1[i];
    for (int i = threadIdx.x; i < 32 * 32; i += blockDim.x) fW2[i] = W.w2[i];
    if (threadIdx.x < 32) {
        fB1[threadIdx.x] = W.b1[threadIdx.x];
        fB2[threadIdx.x] = W.b2[threadIdx.x];
        fW3[threadIdx.x] = W.w3[threadIdx.x];
    }
    __syncthreads();

    int n = blockIdx.x * blockDim.x + threadIdx.x;
    if (n >= N) return;

    float x0 = x[(size_t)n * T_FRAMES * 2 + 0];
    float in9[9] = {x0, 0.f, 0.f, 0.f, 0.f, 0.f, 0.f, 0.f, 0.f};
    g_v[n] = mlp1_eval(in9, sW1, sB1, sW2, sB2, sW3, W.b3[0]);

    g_h[n * 2 + 0] = make_float4(0.f, 0.f, 0.f, 0.f);
    g_h[n * 2 + 1] = make_float4(0.f, 0.f, 0.f, 0.f);
    g_agg[n] = 0.f;
}

// ---------------------------------------------------------------------------
// Edge scatter: 8 edges/thread. msg = v[src]*eaT[t][e]; atomicAdd agg[dst].
// ---------------------------------------------------------------------------
__global__ void __launch_bounds__(256) edge_kernel(
    const int* __restrict__ ei, int E, int t)
{
    int i = blockIdx.x * blockDim.x + threadIdx.x;
    int e0 = i * 8;
    const int* srcb = &ei[((size_t)0 * T_FRAMES + t) * (size_t)E];
    const int* dstb = &ei[((size_t)1 * T_FRAMES + t) * (size_t)E];
    if (e0 + 7 < E) {
        int4 s0 = *(const int4*)&srcb[e0];
        int4 s1 = *(const int4*)&srcb[e0 + 4];
        int4 d0 = *(const int4*)&dstb[e0];
        int4 d1 = *(const int4*)&dstb[e0 + 4];
        float4 a0 = *(const float4*)&g_eaT[(size_t)t * E + e0];
        float4 a1 = *(const float4*)&g_eaT[(size_t)t * E + e0 + 4];
        float v0 = __ldg(&g_v[s0.x]);
        float v1 = __ldg(&g_v[s0.y]);
        float v2 = __ldg(&g_v[s0.z]);
        float v3 = __ldg(&g_v[s0.w]);
        float v4 = __ldg(&g_v[s1.x]);
        float v5 = __ldg(&g_v[s1.y]);
        float v6 = __ldg(&g_v[s1.z]);
        float v7 = __ldg(&g_v[s1.w]);
        atomicAdd(&g_agg[d0.x], v0 * a0.x);
        atomicAdd(&g_agg[d0.y], v1 * a0.y);
        atomicAdd(&g_agg[d0.z], v2 * a0.z);
        atomicAdd(&g_agg[d0.w], v3 * a0.w);
        atomicAdd(&g_agg[d1.x], v4 * a1.x);
        atomicAdd(&g_agg[d1.y], v5 * a1.y);
        atomicAdd(&g_agg[d1.z], v6 * a1.z);
        atomicAdd(&g_agg[d1.w], v7 * a1.w);
    } else {
        for (int e = e0; e < E; e++) {
            atomicAdd(&g_agg[dstb[e]], __ldg(&g_v[srcb[e]]) * g_eaT[(size_t)t * E + e]);
        }
    }
}

// ---------------------------------------------------------------------------
// Node kernel (frame t): FOUR threads per node. Lane q in [0,4) owns packed
// output-channel pairs [4q,4q+4) of each 32-wide layer (and [2q,2q+2) of the
// 16-wide head). Cross-lane combines via xor-1/xor-2 butterflies.
// ---------------------------------------------------------------------------
__global__ void __launch_bounds__(256) node_kernel(
    const float* __restrict__ x, NodeW W, EdgeW EW,
    float* __restrict__ out, int N, int t)
{
    // node weights (packed-j views)
    __shared__ u64 sW1[10 * 16], sB1[16], sW2[32 * 4], sB2[4];
    __shared__ u64 sO1[8 * 8], sOB1[8], sO2[8];
    // edge weights for next-frame v
    __shared__ u64 eW1[9 * 16], eB1[16], eW2[32 * 16], eB2[16], eW3[16];
    __shared__ float sOB2, eB3;

    {
        float* f;
        f = (float*)sW1; for (int i = threadIdx.x; i < 10 * 32; i += blockDim.x) f[i] = W.w1[i];
        f = (float*)sW2; for (int i = threadIdx.x; i < 32 * 8;  i += blockDim.x) f[i] = W.w2[i];
        f = (float*)sO1; for (int i = threadIdx.x; i < 8 * 16;  i += blockDim.x) f[i] = W.ow1[i];
        f = (float*)eW1; for (int i = threadIdx.x; i < 9 * 32;  i += blockDim.x) f[i] = EW.w1[i];
        f = (float*)eW2; for (int i = threadIdx.x; i < 32 * 32; i += blockDim.x) f[i] = EW.w2[i];
        if (threadIdx.x < 32) {
            ((float*)sB1)[threadIdx.x] = W.b1[threadIdx.x];
            ((float*)eB1)[threadIdx.x] = EW.b1[threadIdx.x];
            ((float*)eB2)[threadIdx.x] = EW.b2[threadIdx.x];
            ((float*)eW3)[threadIdx.x] = EW.w3[threadIdx.x];
        }
        if (threadIdx.x < 16) {
            ((float*)sOB1)[threadIdx.x] = W.ob1[threadIdx.x];
            ((float*)sO2)[threadIdx.x]  = W.ow2[threadIdx.x];
        }
        if (threadIdx.x < 8) ((float*)sB2)[threadIdx.x] = W.b2[threadIdx.x];
        if (threadIdx.x == 0) { sOB2 = W.ob2[0]; eB3 = EW.b3[0]; }
    }
    __syncthreads();

    int gid = blockIdx.x * blockDim.x + threadIdx.x;
    int n = gid >> 2;
    int q = gid & 3;
    bool valid = (n < N);
    int nc = valid ? n : (N - 1);          // clamp; no early exit (shuffles!)
    int jb = q * 4;                        // packed-pair base for 32-wide layers

    float4 ha = g_h[nc * 2 + 0];
    float4 hb = g_h[nc * 2 + 1];
    float aggv = g_agg[nc];
    if (valid && q == 0) g_agg[n] = 0.f;   // reset for next frame
    float x1 = x[(size_t)nc * T_FRAMES * 2 + (size_t)t * 2 + 1];

    float in10[10] = {x1, ha.x, ha.y, ha.z, ha.w, hb.x, hb.y, hb.z, hb.w, aggv};

    // ---- MLP2 layer1: 10 -> 32, this lane's 4 pairs ----
    u64 u[4];
#pragma unroll
    for (int j = 0; j < 4; j++) u[j] = sB1[jb + j];
#pragma unroll
    for (int k = 0; k < 10; k++) {
        u64 v = pk2(in10[k], in10[k]);
#pragma unroll
        for (int j = 0; j < 4; j++) u[j] = ffma2(v, sW1[k * 16 + jb + j], u[j]);
    }
#pragma unroll
    for (int j = 0; j < 4; j++) u[j] = relu2(u[j]);

    // ---- MLP2 layer2: 32 -> 8; partial over this lane's 8 input channels ----
    u64 a2[4];
#pragma unroll
    for (int j = 0; j < 4; j++) a2[j] = (q == 0) ? sB2[j] : pk2(0.f, 0.f);
#pragma unroll
    for (int kp = 0; kp < 4; kp++) {
        int c0 = 2 * (jb + kp);            // global input channel
        float va, vb; upk2(u[kp], va, vb);
        u64 pa = pk2(va, va), pb = pk2(vb, vb);
#pragma unroll
        for (int j = 0; j < 4; j++) a2[j] = ffma2(pa, sW2[c0 * 4 + j], a2[j]);
#pragma unroll
        for (int j = 0; j < 4; j++) a2[j] = ffma2(pb, sW2[(c0 + 1) * 4 + j], a2[j]);
    }
#pragma unroll
    for (int j = 0; j < 4; j++) a2[j] = add2(a2[j], shflx_u64(a2[j], 1));
#pragma unroll
    for (int j = 0; j < 4; j++) a2[j] = add2(a2[j], shflx_u64(a2[j], 2));

    float hn[HID];
#pragma unroll
    for (int j = 0; j < 4; j++) {
        float va, vb; upk2(a2[j], va, vb);
        hn[2 * j + 0] = tanhf_(fmaxf(va, 0.f));
        hn[2 * j + 1] = tanhf_(fmaxf(vb, 0.f));
    }

    // ---- Output head: 8 -> 16 -> 1; this lane's 2 pairs ----
    int ob2 = q * 2;
    u64 o[2];
#pragma unroll
    for (int j = 0; j < 2; j++) o[j] = sOB1[ob2 + j];
#pragma unroll
    for (int k = 0; k < 8; k++) {
        u64 v = pk2(hn[k], hn[k]);
#pragma unroll
        for (int j = 0; j < 2; j++) o[j] = ffma2(v, sO1[k * 8 + ob2 + j], o[j]);
    }
    u64 sp = pk2(0.f, 0.f);
#pragma unroll
    for (int j = 0; j < 2; j++) sp = ffma2(relu2(o[j]), sO2[ob2 + j], sp);
    float sa, sb; upk2(sp, sa, sb);
    float spart = sa + sb;
    spart += __shfl_xor_sync(0xFFFFFFFFu, spart, 1);
    spart += __shfl_xor_sync(0xFFFFFFFFu, spart, 2);
    if (valid && q == 0) {
        out[(size_t)t * N + n] = sigmoidf_(spart + sOB2);
        g_h[n * 2 + 0] = make_float4(hn[0], hn[1], hn[2], hn[3]);
        g_h[n * 2 + 1] = make_float4(hn[4], hn[5], hn[6], hn[7]);
    }

    // ---- MLP1 for next frame's v ----
    if (t + 1 < T_FRAMES) {
        float x0n = x[(size_t)nc * T_FRAMES * 2 + (size_t)(t + 1) * 2 + 0];
        float in9[9] = {x0n, hn[0], hn[1], hn[2], hn[3], hn[4], hn[5], hn[6], hn[7]};

        // layer1: this lane's 4 pairs
        u64 mine[4];
#pragma unroll
        for (int j = 0; j < 4; j++) mine[j] = eB1[jb + j];
#pragma unroll
        for (int k = 0; k < 9; k++) {
            u64 v = pk2(in9[k], in9[k]);
#pragma unroll
            for (int j = 0; j < 4; j++) mine[j] = ffma2(v, eW1[k * 16 + jb + j], mine[j]);
        }
#pragma unroll
        for (int j = 0; j < 4; j++) mine[j] = relu2(mine[j]);

        // butterfly assembly of all 16 hidden pairs
        u64 o1[4];
#pragma unroll
        for (int j = 0; j < 4; j++) o1[j] = shflx_u64(mine[j], 1);
        u64 h8lo[4], h8hi[4];
#pragma unroll
        for (int j = 0; j < 4; j++) {
            h8lo[j] = (q & 1) ? o1[j] : mine[j];
            h8hi[j] = (q & 1) ? mine[j] : o1[j];
        }
        u64 o2lo[4], o2hi[4];
#pragma unroll
        for (int j = 0; j < 4; j++) o2lo[j] = shflx_u64(h8lo[j], 2);
#pragma unroll
        for (int j = 0; j < 4; j++) o2hi[j] = shflx_u64(h8hi[j], 2);

        u64 h16[16];
#pragma unroll
        for (int j = 0; j < 4; j++) {
            h16[j]      = (q < 2) ? h8lo[j] : o2lo[j];
            h16[4 + j]  = (q < 2) ? h8hi[j] : o2hi[j];
            h16[8 + j]  = (q < 2) ? o2lo[j] : h8lo[j];
            h16[12 + j] = (q < 2) ? o2hi[j] : h8hi[j];
        }

        // layer2: this lane's 4 output pairs over all 32 input channels
        u64 acc[4];
#pragma unroll
        for (int j = 0; j < 4; j++) acc[j] = eB2[jb + j];
#pragma unroll
        for (int cp = 0; cp < 16; cp++) {
            float va, vb; upk2(h16[cp], va, vb);
            u64 pa = pk2(va, va), pb = pk2(vb, vb);
#pragma unroll
            for (int j = 0; j < 4; j++)
                acc[j] = ffma2(pa, eW2[(2 * cp) * 16 + jb + j], acc[j]);
#pragma unroll
            for (int j = 0; j < 4; j++)
                acc[j] = ffma2(pb, eW2[(2 * cp + 1) * 16 + jb + j], acc[j]);
        }

        u64 vp = pk2(0.f, 0.f);
#pragma unroll
        for (int j = 0; j < 4; j++) vp = ffma2(relu2(acc[j]), eW3[jb + j], vp);
        float va, vb; upk2(vp, va, vb);
        float vpart = va + vb;
        vpart += __shfl_xor_sync(0xFFFFFFFFu, vpart, 1);
        vpart += __shfl_xor_sync(0xFFFFFFFFu, vpart, 2);
        if (valid && q == 0) g_v[n] = sigmoidf_(vpart + eB3);
    }
}

// ---------------------------------------------------------------------------
extern "C" void kernel_launch(void* const* d_in, const int* in_sizes, int n_in,
                              void* d_out, int out_size)
{
    const float* x  = (const float*)d_in[0];
    const int*   ei = (const int*)  d_in[1];
    const float* ea = (const float*)d_in[2];

    EdgeW ew;
    ew.w1 = (const float*)d_in[3];  ew.b1 = (const float*)d_in[4];
    ew.w2 = (const float*)d_in[5];  ew.b2 = (const float*)d_in[6];
    ew.w3 = (const float*)d_in[7];  ew.b3 = (const float*)d_in[8];

    NodeW nw;
    nw.w1  = (const float*)d_in[9];  nw.b1  = (const float*)d_in[10];
    nw.w2  = (const float*)d_in[11]; nw.b2  = (const float*)d_in[12];
    nw.ow1 = (const float*)d_in[13]; nw.ob1 = (const float*)d_in[14];
    nw.ow2 = (const float*)d_in[15]; nw.ob2 = (const float*)d_in[16];

    float* out = (float*)d_out;

    int N = out_size / T_FRAMES;          // 50000
    int E = in_sizes[2] / T_FRAMES;       // 1000000

    int nb = (N + 255) / 256;
    int nb4 = (4 * N + 255) / 256;        // 4 threads per node
    int eb = ((E + 7) / 8 + 255) / 256;
    int tb = (E + 255) / 256;

    transpose_ea_kernel<<<tb, 256>>>(ea, E);
    init_kernel<<<nb, 256>>>(x, ew, N);
    for (int t = 0; t < T_FRAMES; t++) {
        edge_kernel<<<eb, 256>>>(ei, E, t);
        node_kernel<<<nb4, 256>>>(x, nw, ew, out, N, t);
    }
}

// round 10
// speedup vs baseline: 1.3984x; 1.3984x over previous
#include <cuda_runtime.h>
#include <math.h>

// Problem constants (AirMPRNN: N=50000, E=1e6, T=10, H=8)
#define T_FRAMES 10
#define HID 8
#define MAXN 65536
#define MAXE 1048576

// Scratch (device globals).
__device__ float4 g_h[MAXN * 2];   // hidden: (h0..h3),(h4..h7)
__device__ float  g_v[MAXN];       // per-node edge-message scalar for current frame
__device__ float  g_agg[MAXN];     // scatter accumulator
__device__ float  g_eaT[(size_t)T_FRAMES * MAXE];  // edge_attr transposed [T][E]

struct EdgeW { const float *w1,*b1,*w2,*b2,*w3,*b3; };
struct NodeW { const float *w1,*b1,*w2,*b2,*ow1,*ob1,*ow2,*ob2; };

typedef unsigned long long u64;

__device__ __forceinline__ float sigmoidf_(float s) {
    return __fdividef(1.0f, 1.0f + __expf(-s));
}
__device__ __forceinline__ float tanhf_(float s) {
    return 1.0f - __fdividef(2.0f, __expf(2.0f * s) + 1.0f);
}

// ---- f32x2 packed helpers ----
__device__ __forceinline__ u64 pk2(float a, float b) {
    u64 r; asm("mov.b64 %0, {%1, %2};" : "=l"(r) : "f"(a), "f"(b)); return r;
}
__device__ __forceinline__ void upk2(u64 v, float& a, float& b) {
    asm("mov.b64 {%0, %1}, %2;" : "=f"(a), "=f"(b) : "l"(v));
}
__device__ __forceinline__ u64 ffma2(u64 a, u64 b, u64 c) {
    u64 d; asm("fma.rn.f32x2 %0, %1, %2, %3;" : "=l"(d) : "l"(a), "l"(b), "l"(c)); return d;
}
__device__ __forceinline__ u64 add2(u64 a, u64 b) {
    u64 d; asm("add.rn.f32x2 %0, %1, %2;" : "=l"(d) : "l"(a), "l"(b)); return d;
}
__device__ __forceinline__ u64 relu2(u64 v) {
    float a, b; upk2(v, a, b);
    return pk2(fmaxf(a, 0.f), fmaxf(b, 0.f));
}
__device__ __forceinline__ u64 shflx1_u64(u64 v) {
    unsigned lo = (unsigned)v, hi = (unsigned)(v >> 32);
    lo = __shfl_xor_sync(0xFFFFFFFFu, lo, 1);
    hi = __shfl_xor_sync(0xFFFFFFFFu, hi, 1);
    return ((u64)hi << 32) | lo;
}

// ---------------------------------------------------------------------------
// Full (single-thread) MLP1 eval — used only by init_kernel.
// ---------------------------------------------------------------------------
__device__ __forceinline__ float mlp1_eval(
    const float* in9,
    const u64* sW1p, const u64* sB1p,
    const u64* sW2p, const u64* sB2p,
    const u64* sW3p, float b3)
{
    u64 h[16];
#pragma unroll
    for (int j = 0; j < 16; j++) h[j] = sB1p[j];
#pragma unroll
    for (int k = 0; k < 9; k++) {
        u64 v = pk2(in9[k], in9[k]);
#pragma unroll
        for (int j = 0; j < 16; j++) h[j] = ffma2(v, sW1p[k * 16 + j], h[j]);
    }
#pragma unroll
    for (int j = 0; j < 16; j++) h[j] = relu2(h[j]);

    u64 acc[16];
#pragma unroll
    for (int j = 0; j < 16; j++) acc[j] = sB2p[j];
#pragma unroll
    for (int kp = 0; kp < 16; kp++) {
        float ha, hb; upk2(h[kp], ha, hb);
        u64 va = pk2(ha, ha), vb = pk2(hb, hb);
#pragma unroll
        for (int j = 0; j < 16; j++)
            acc[j] = ffma2(va, sW2p[(2 * kp) * 16 + j], acc[j]);
#pragma unroll
        for (int j = 0; j < 16; j++)
            acc[j] = ffma2(vb, sW2p[(2 * kp + 1) * 16 + j], acc[j]);
    }

    u64 s = pk2(0.f, 0.f);
#pragma unroll
    for (int j = 0; j < 16; j++) s = ffma2(relu2(acc[j]), sW3p[j], s);
    float s0, s1; upk2(s, s0, s1);
    return sigmoidf_(s0 + s1 + b3);
}

// ---------------------------------------------------------------------------
// ea transpose: [E,T] -> [T][E].
// ---------------------------------------------------------------------------
__global__ void __launch_bounds__(256) transpose_ea_kernel(
    const float* __restrict__ ea, int E)
{
    __shared__ float tile[256 * T_FRAMES];
    int base = blockIdx.x * 256;
    int cnt = min(256, E - base);
    int nflt = cnt * T_FRAMES;

    for (int i = threadIdx.x; i < nflt; i += 256)
        tile[i] = ea[(size_t)base * T_FRAMES + i];
    __syncthreads();

#pragma unroll
    for (int t = 0; t < T_FRAMES; t++) {
        if (threadIdx.x < cnt)
            g_eaT[(size_t)t * E + base + threadIdx.x] =
                tile[threadIdx.x * T_FRAMES + t];
    }
}

// ---------------------------------------------------------------------------
// Init: hidden = 0, agg = 0, v0 = sigmoid(MLP1([x0(t=0), 0..0]))
// ---------------------------------------------------------------------------
__global__ void __launch_bounds__(256) init_kernel(
    const float* __restrict__ x, EdgeW W, int N)
{
    __shared__ u64 sW1[9 * 16], sB1[16], sW2[32 * 16], sB2[16], sW3[16];
    float* fW1 = (float*)sW1; float* fB1 = (float*)sB1;
    float* fW2 = (float*)sW2; float* fB2 = (float*)sB2;
    float* fW3 = (float*)sW3;
    for (int i = threadIdx.x; i < 9 * 32; i += blockDim.x)  fW1[i] = W.w1[i];
    for (int i = threadIdx.x; i < 32 * 32; i += blockDim.x) fW2[i] = W.w2[i];
    if (threadIdx.x < 32) {
        fB1[threadIdx.x] = W.b1[threadIdx.x];
        fB2[threadIdx.x] = W.b2[threadIdx.x];
        fW3[threadIdx.x] = W.w3[threadIdx.x];
    }
    __syncthreads();

    int n = blockIdx.x * blockDim.x + threadIdx.x;
    if (n >= N) return;

    float x0 = x[(size_t)n * T_FRAMES * 2 + 0];
    float in9[9] = {x0, 0.f, 0.f, 0.f, 0.f, 0.f, 0.f, 0.f, 0.f};
    g_v[n] = mlp1_eval(in9, sW1, sB1, sW2, sB2, sW3, W.b3[0]);

    g_h[n * 2 + 0] = make_float4(0.f, 0.f, 0.f, 0.f);
    g_h[n * 2 + 1] = make_float4(0.f, 0.f, 0.f, 0.f);
    g_agg[n] = 0.f;
}

// ---------------------------------------------------------------------------
// Edge scatter: 16 edges/thread. msg = v[src]*eaT[t][e]; atomicAdd agg[dst].
// ---------------------------------------------------------------------------
__global__ void __launch_bounds__(256) edge_kernel(
    const int* __restrict__ ei, int E, int t)
{
    int i = blockIdx.x * blockDim.x + threadIdx.x;
    int e0 = i * 16;
    const int* srcb = &ei[((size_t)0 * T_FRAMES + t) * (size_t)E];
    const int* dstb = &ei[((size_t)1 * T_FRAMES + t) * (size_t)E];
    const float* eab = &g_eaT[(size_t)t * E];
    if (e0 + 15 < E) {
        int4 s[4]; int4 d[4]; float4 a[4];
#pragma unroll
        for (int c = 0; c < 4; c++) {
            s[c] = *(const int4*)&srcb[e0 + 4 * c];
            d[c] = *(const int4*)&dstb[e0 + 4 * c];
            a[c] = *(const float4*)&eab[e0 + 4 * c];
        }
        float v[16];
#pragma unroll
        for (int c = 0; c < 4; c++) {
            v[4 * c + 0] = __ldg(&g_v[s[c].x]);
            v[4 * c + 1] = __ldg(&g_v[s[c].y]);
            v[4 * c + 2] = __ldg(&g_v[s[c].z]);
            v[4 * c + 3] = __ldg(&g_v[s[c].w]);
        }
#pragma unroll
        for (int c = 0; c < 4; c++) {
            atomicAdd(&g_agg[d[c].x], v[4 * c + 0] * a[c].x);
            atomicAdd(&g_agg[d[c].y], v[4 * c + 1] * a[c].y);
            atomicAdd(&g_agg[d[c].z], v[4 * c + 2] * a[c].z);
            atomicAdd(&g_agg[d[c].w], v[4 * c + 3] * a[c].w);
        }
    } else {
        for (int e = e0; e < E; e++)
            atomicAdd(&g_agg[dstb[e]], __ldg(&g_v[srcb[e]]) * eab[e]);
    }
}

// ---------------------------------------------------------------------------
// Node kernel (frame t): thread-PAIR (lane q in {0,1}) processes TWO nodes.
// Lane q owns packed output-channel pairs [8q,8q+8) of the 32-wide layers.
// Each weight LDS feeds ffma2 for both nodes (2x reuse). xor-1 butterflies.
// ---------------------------------------------------------------------------
__global__ void __launch_bounds__(256) node_kernel(
    const float* __restrict__ x, NodeW W, EdgeW EW,
    float* __restrict__ out, int N, int t)
{
    // node weights (packed-j views)
    __shared__ u64 sW1[10 * 16], sB1[16], sW2[32 * 4], sB2[4];
    __shared__ u64 sO1[8 * 8], sOB1[8], sO2[8];
    // edge weights for next-frame v
    __shared__ u64 eW1[9 * 16], eB1[16], eW2[32 * 16], eB2[16], eW3[16];
    __shared__ float sOB2, eB3;

    {
        float* f;
        f = (float*)sW1; for (int i = threadIdx.x; i < 10 * 32; i += blockDim.x) f[i] = W.w1[i];
        f = (float*)sW2; for (int i = threadIdx.x; i < 32 * 8;  i += blockDim.x) f[i] = W.w2[i];
        f = (float*)sO1; for (int i = threadIdx.x; i < 8 * 16;  i += blockDim.x) f[i] = W.ow1[i];
        f = (float*)eW1; for (int i = threadIdx.x; i < 9 * 32;  i += blockDim.x) f[i] = EW.w1[i];
        f = (float*)eW2; for (int i = threadIdx.x; i < 32 * 32; i += blockDim.x) f[i] = EW.w2[i];
        if (threadIdx.x < 32) {
            ((float*)sB1)[threadIdx.x] = W.b1[threadIdx.x];
            ((float*)eB1)[threadIdx.x] = EW.b1[threadIdx.x];
            ((float*)eB2)[threadIdx.x] = EW.b2[threadIdx.x];
            ((float*)eW3)[threadIdx.x] = EW.w3[threadIdx.x];
        }
        if (threadIdx.x < 16) {
            ((float*)sOB1)[threadIdx.x] = W.ob1[threadIdx.x];
            ((float*)sO2)[threadIdx.x]  = W.ow2[threadIdx.x];
        }
        if (threadIdx.x < 8) ((float*)sB2)[threadIdx.x] = W.b2[threadIdx.x];
        if (threadIdx.x == 0) { sOB2 = W.ob2[0]; eB3 = EW.b3[0]; }
    }
    __syncthreads();

    int gid = blockIdx.x * blockDim.x + threadIdx.x;
    int p = gid >> 1;                      // pair index -> nodes 2p, 2p+1
    int q = gid & 1;
    int n0 = 2 * p;
    int n1 = 2 * p + 1;
    bool v0ok = (n0 < N), v1ok = (n1 < N);
    int c0 = v0ok ? n0 : 0, c1 = v1ok ? n1 : 0;  // clamp; no early exit
    int jb = q * 8;                        // packed-pair base for 32-wide layers

    float4 ha0 = g_h[c0 * 2 + 0], hb0 = g_h[c0 * 2 + 1];
    float4 ha1 = g_h[c1 * 2 + 0], hb1 = g_h[c1 * 2 + 1];
    float ag0 = g_agg[c0], ag1 = g_agg[c1];
    if (q == 0) {
        if (v0ok) g_agg[n0] = 0.f;
        if (v1ok) g_agg[n1] = 0.f;
    }
    float x1_0 = x[(size_t)c0 * T_FRAMES * 2 + (size_t)t * 2 + 1];
    float x1_1 = x[(size_t)c1 * T_FRAMES * 2 + (size_t)t * 2 + 1];

    float in0[10] = {x1_0, ha0.x, ha0.y, ha0.z, ha0.w, hb0.x, hb0.y, hb0.z, hb0.w, ag0};
    float in1[10] = {x1_1, ha1.x, ha1.y, ha1.z, ha1.w, hb1.x, hb1.y, hb1.z, hb1.w, ag1};

    // ---- MLP2 layer1: 10 -> 32, this lane's 8 pairs, both nodes ----
    u64 u0[8], u1[8];
#pragma unroll
    for (int j = 0; j < 8; j++) { u64 b = sB1[jb + j]; u0[j] = b; u1[j] = b; }
#pragma unroll
    for (int k = 0; k < 10; k++) {
        u64 va = pk2(in0[k], in0[k]);
        u64 vb = pk2(in1[k], in1[k]);
#pragma unroll
        for (int j = 0; j < 8; j++) {
            u64 w = sW1[k * 16 + jb + j];
            u0[j] = ffma2(va, w, u0[j]);
            u1[j] = ffma2(vb, w, u1[j]);
        }
    }
#pragma unroll
    for (int j = 0; j < 8; j++) { u0[j] = relu2(u0[j]); u1[j] = relu2(u1[j]); }

    // ---- MLP2 layer2: 32 -> 8; partial over this lane's 16 input channels ----
    u64 a20[4], a21[4];
#pragma unroll
    for (int j = 0; j < 4; j++) {
        u64 b = (q == 0) ? sB2[j] : pk2(0.f, 0.f);
        a20[j] = b; a21[j] = (q == 0) ? sB2[j] : pk2(0.f, 0.f);
    }
#pragma unroll
    for (int j = 0; j < 4; j++) a21[j] = (q == 0) ? sB2[j] : pk2(0.f, 0.f);
    // NOTE: a20 initialized with bias only on node0's lane-0; a21 likewise.
#pragma unroll
    for (int j = 0; j < 4; j++) { if (q != 0) { a20[j] = pk2(0.f,0.f); a21[j] = pk2(0.f,0.f);} }
#pragma unroll
    for (int kp = 0; kp < 8; kp++) {
        int cc = 2 * (jb + kp);            // global input channel
        float va0, vb0; upk2(u0[kp], va0, vb0);
        float va1, vb1; upk2(u1[kp], va1, vb1);
        u64 pa0 = pk2(va0, va0), pb0 = pk2(vb0, vb0);
        u64 pa1 = pk2(va1, va1), pb1 = pk2(vb1, vb1);
#pragma unroll
        for (int j = 0; j < 4; j++) {
            u64 wa = sW2[cc * 4 + j];
            u64 wb = sW2[(cc + 1) * 4 + j];
            a20[j] = ffma2(pa0, wa, a20[j]);
            a21[j] = ffma2(pa1, wa, a21[j]);
            a20[j] = ffma2(pb0, wb, a20[j]);
            a21[j] = ffma2(pb1, wb, a21[j]);
        }
    }
#pragma unroll
    for (int j = 0; j < 4; j++) a20[j] = add2(a20[j], shflx1_u64(a20[j]));
#pragma unroll
    for (int j = 0; j < 4; j++) a21[j] = add2(a21[j], shflx1_u64(a21[j]));

    float hn0[HID], hn1[HID];
#pragma unroll
    for (int j = 0; j < 4; j++) {
        float va, vb;
        upk2(a20[j], va, vb);
        hn0[2 * j + 0] = tanhf_(fmaxf(va, 0.f));
        hn0[2 * j + 1] = tanhf_(fmaxf(vb, 0.f));
        upk2(a21[j], va, vb);
        hn1[2 * j + 0] = tanhf_(fmaxf(va, 0.f));
        hn1[2 * j + 1] = tanhf_(fmaxf(vb, 0.f));
    }

    // ---- Output head: 8 -> 16 -> 1; this lane's 4 pairs, both nodes ----
    int ob4 = q * 4;
    u64 o0[4], o1[4];
#pragma unroll
    for (int j = 0; j < 4; j++) { u64 b = sOB1[ob4 + j]; o0[j] = b; o1[j] = b; }
#pragma unroll
    for (int k = 0; k < 8; k++) {
        u64 va = pk2(hn0[k], hn0[k]);
        u64 vb = pk2(hn1[k], hn1[k]);
#pragma unroll
        for (int j = 0; j < 4; j++) {
            u64 w = sO1[k * 8 + ob4 + j];
            o0[j] = ffma2(va, w, o0[j]);
            o1[j] = ffma2(vb, w, o1[j]);
        }
    }
    u64 sp0 = pk2(0.f, 0.f), sp1 = pk2(0.f, 0.f);
#pragma unroll
    for (int j = 0; j < 4; j++) {
        u64 w = sO2[ob4 + j];
        sp0 = ffma2(relu2(o0[j]), w, sp0);
        sp1 = ffma2(relu2(o1[j]), w, sp1);
    }
    float sa, sb;
    upk2(sp0, sa, sb); float spart0 = sa + sb;
    upk2(sp1, sa, sb); float spart1 = sa + sb;
    spart0 += __shfl_xor_sync(0xFFFFFFFFu, spart0, 1);
    spart1 += __shfl_xor_sync(0xFFFFFFFFu, spart1, 1);
    if (q == 0) {
        if (v0ok) {
            out[(size_t)t * N + n0] = sigmoidf_(spart0 + sOB2);
            g_h[n0 * 2 + 0] = make_float4(hn0[0], hn0[1], hn0[2], hn0[3]);
            g_h[n0 * 2 + 1] = make_float4(hn0[4], hn0[5], hn0[6], hn0[7]);
        }
        if (v1ok) {
            out[(size_t)t * N + n1] = sigmoidf_(spart1 + sOB2);
            g_h[n1 * 2 + 0] = make_float4(hn1[0], hn1[1], hn1[2], hn1[3]);
            g_h[n1 * 2 + 1] = make_float4(hn1[4], hn1[5], hn1[6], hn1[7]);
        }
    }

    // ---- MLP1 for next frame's v, both nodes ----
    if (t + 1 < T_FRAMES) {
        float x0_0 = x[(size_t)c0 * T_FRAMES * 2 + (size_t)(t + 1) * 2 + 0];
        float x0_1 = x[(size_t)c1 * T_FRAMES * 2 + (size_t)(t + 1) * 2 + 0];
        float i90[9] = {x0_0, hn0[0], hn0[1], hn0[2], hn0[3], hn0[4], hn0[5], hn0[6], hn0[7]};
        float i91[9] = {x0_1, hn1[0], hn1[1], hn1[2], hn1[3], hn1[4], hn1[5], hn1[6], hn1[7]};

        // layer1: this lane's 8 pairs, both nodes
        u64 h0[8], h1[8];
#pragma unroll
        for (int j = 0; j < 8; j++) { u64 b = eB1[jb + j]; h0[j] = b; h1[j] = b; }
#pragma unroll
        for (int k = 0; k < 9; k++) {
            u64 va = pk2(i90[k], i90[k]);
            u64 vb = pk2(i91[k], i91[k]);
#pragma unroll
            for (int j = 0; j < 8; j++) {
                u64 w = eW1[k * 16 + jb + j];
                h0[j] = ffma2(va, w, h0[j]);
                h1[j] = ffma2(vb, w, h1[j]);
            }
        }
#pragma unroll
        for (int j = 0; j < 8; j++) { h0[j] = relu2(h0[j]); h1[j] = relu2(h1[j]); }

        // layer2: this lane's 8 output pairs, accumulate own channels first
        u64 acc0[8], acc1[8];
#pragma unroll
        for (int j = 0; j < 8; j++) { u64 b = eB2[jb + j]; acc0[j] = b; acc1[j] = b; }

        int base_own = 2 * jb;             // own channels: [16q, 16q+16)
#pragma unroll
        for (int kp = 0; kp < 8; kp++) {
            int cc = base_own + 2 * kp;
            float va0, vb0; upk2(h0[kp], va0, vb0);
            float va1, vb1; upk2(h1[kp], va1, vb1);
            u64 pa0 = pk2(va0, va0), pb0 = pk2(vb0, vb0);
            u64 pa1 = pk2(va1, va1), pb1 = pk2(vb1, vb1);
#pragma unroll
            for (int j = 0; j < 8; j++) {
                u64 wa = eW2[cc * 16 + jb + j];
                u64 wb = eW2[(cc + 1) * 16 + jb + j];
                acc0[j] = ffma2(pa0, wa, acc0[j]);
                acc1[j] = ffma2(pa1, wa, acc1[j]);
                acc0[j] = ffma2(pb0, wb, acc0[j]);
                acc1[j] = ffma2(pb1, wb, acc1[j]);
            }
        }

        // swap h with partner lane (in place), accumulate partner channels
#pragma unroll
        for (int j = 0; j < 8; j++) { h0[j] = shflx1_u64(h0[j]); h1[j] = shflx1_u64(h1[j]); }
        int base_par = 2 * (8 - jb);       // partner channels
#pragma unroll
        for (int kp = 0; kp < 8; kp++) {
            int cc = base_par + 2 * kp;
            float va0, vb0; upk2(h0[kp], va0, vb0);
            float va1, vb1; upk2(h1[kp], va1, vb1);
            u64 pa0 = pk2(va0, va0), pb0 = pk2(vb0, vb0);
            u64 pa1 = pk2(va1, va1), pb1 = pk2(vb1, vb1);
#pragma unroll
            for (int j = 0; j < 8; j++) {
                u64 wa = eW2[cc * 16 + jb + j];
                u64 wb = eW2[(cc + 1) * 16 + jb + j];
                acc0[j] = ffma2(pa0, wa, acc0[j]);
                acc1[j] = ffma2(pa1, wa, acc1[j]);
                acc0[j] = ffma2(pb0, wb, acc0[j]);
                acc1[j] = ffma2(pb1, wb, acc1[j]);
            }
        }

        u64 vp0 = pk2(0.f, 0.f), vp1 = pk2(0.f, 0.f);
#pragma unroll
        for (int j = 0; j < 8; j++) {
            u64 w = eW3[jb + j];
            vp0 = ffma2(relu2(acc0[j]), w, vp0);
            vp1 = ffma2(relu2(acc1[j]), w, vp1);
        }
        float va, vb;
        upk2(vp0, va, vb); float vpart0 = va + vb;
        upk2(vp1, va, vb); float vpart1 = va + vb;
        vpart0 += __shfl_xor_sync(0xFFFFFFFFu, vpart0, 1);
        vpart1 += __shfl_xor_sync(0xFFFFFFFFu, vpart1, 1);
        if (q == 0) {
            if (v0ok) g_v[n0] = sigmoidf_(vpart0 + eB3);
            if (v1ok) g_v[n1] = sigmoidf_(vpart1 + eB3);
        }
    }
}

// ---------------------------------------------------------------------------
extern "C" void kernel_launch(void* const* d_in, const int* in_sizes, int n_in,
                              void* d_out, int out_size)
{
    const float* x  = (const float*)d_in[0];
    const int*   ei = (const int*)  d_in[1];
    const float* ea = (const float*)d_in[2];

    EdgeW ew;
    ew.w1 = (const float*)d_in[3];  ew.b1 = (const float*)d_in[4];
    ew.w2 = (const float*)d_in[5];  ew.b2 = (const float*)d_in[6];
    ew.w3 = (const float*)d_in[7];  ew.b3 = (const float*)d_in[8];

    NodeW nw;
    nw.w1  = (const float*)d_in[9];  nw.b1  = (const float*)d_in[10];
    nw.w2  = (const float*)d_in[11]; nw.b2  = (const float*)d_in[12];
    nw.ow1 = (const float*)d_in[13]; nw.ob1 = (const float*)d_in[14];
    nw.ow2 = (const float*)d_in[15]; nw.ob2 = (const float*)d_in[16];

    float* out = (float*)d_out;

    int N = out_size / T_FRAMES;          // 50000
    int E = in_sizes[2] / T_FRAMES;       // 1000000

    int nb = (N + 255) / 256;
    int npairs = (N + 1) / 2;
    int nbp = (2 * npairs + 255) / 256;   // 2 threads per pair of nodes
    int eb = ((E + 15) / 16 + 255) / 256;
    int tb = (E + 255) / 256;

    transpose_ea_kernel<<<tb, 256>>>(ea, E);
    init_kernel<<<nb, 256>>>(x, ew, N);
    for (int t = 0; t < T_FRAMES; t++) {
        edge_kernel<<<eb, 256>>>(ei, E, t);
        node_kernel<<<nbp, 256>>>(x, nw, ew, out, N, t);
    }
}